// round 2
// baseline (speedup 1.0000x reference)
#include <cuda_runtime.h>
#include <math.h>

#define BB 2
#define C 19
#define H 128
#define W 128
#define HW (H*W)          // 16384
#define CF 256
#define SH 64
#define SW 64
#define SP (SH*SW)        // 4096

#define TW 16             // main-kernel tile width
#define TH 8              // main-kernel tile height
#define NBLK ((W/TW)*(H/TH)*BB)   // 8*16*2 = 256
#define HALO_W (TW+2)     // 18
#define HALO_H (TH+2)     // 10
#define HALO_N (HALO_W*HALO_H)    // 180

// Scratch (static device globals; no allocations)
__device__ float  g_tf[BB*SP*CF];        // transposed feats [b][s][c]
__device__ float  g_sim[BB*SP*9];        // per-source sims: 8 dirs + [4]=exp(-||f||^2)
__device__ double g_partial[3*NBLK];     // per-block partials
__device__ int    g_count = 0;           // last-block counter (self-resetting)

// ---------------- K1: transpose feats [b][c][p] -> [b][p][c] ----------------
__global__ void k_transpose(const float* __restrict__ feats) {
    __shared__ float tile[32][33];
    int b  = blockIdx.z;
    int p0 = blockIdx.x * 32;
    int c0 = blockIdx.y * 32;
    int tx = threadIdx.x, ty = threadIdx.y;
    tile[ty][tx] = feats[(size_t)b * CF * SP + (size_t)(c0 + ty) * SP + (p0 + tx)];
    __syncthreads();
    g_tf[(size_t)b * SP * CF + (size_t)(p0 + ty) * CF + (c0 + tx)] = tile[tx][ty];
}

// ---------------- K2: source-pixel sims, symmetry-halved (warp per source) --
// forward dirs computed: k=5 (0,+1), k=6 (+1,-1), k=7 (+1,0), k=8 (+1,+1).
// mirror slot for neighbor: 8-k. Backward slot k in {0..3} written as 0 here
// only when the backward neighbor is out of range (else that neighbor writes it).
__global__ void k_srcsim() {
    int gw   = (blockIdx.x * blockDim.x + threadIdx.x) >> 5;
    int lane = threadIdx.x & 31;
    if (gw >= BB * SP) return;
    int b  = gw / SP;
    int s  = gw % SP;
    int sh = s >> 6, sw = s & 63;

    const float4* base = reinterpret_cast<const float4*>(g_tf + (size_t)(b * SP + s) * CF);
    float4 a0 = base[lane];
    float4 a1 = base[lane + 32];

    float acc = a0.x*a0.x + a0.y*a0.y + a0.z*a0.z + a0.w*a0.w
              + a1.x*a1.x + a1.y*a1.y + a1.z*a1.z + a1.w*a1.w;
    #pragma unroll
    for (int o = 16; o > 0; o >>= 1) acc += __shfl_xor_sync(0xffffffffu, acc, o);
    float* simout = g_sim + (size_t)(b * SP + s) * 9;
    if (lane == 0) {
        simout[4] = expf(-acc);
        // backward slots whose backward neighbor is OOB -> 0
        if (sh == 0)            { simout[0] = 0.f; simout[1] = 0.f; simout[2] = 0.f; }
        else {
            if (sw == 0)          simout[0] = 0.f;
            if (sw == SW - 1)     simout[2] = 0.f;
        }
        if (sw == 0)              simout[3] = 0.f;
    }

    const int fdr[4] = {0, 1, 1, 1};
    const int fdc[4] = {1, -1, 0, 1};
    const int fk [4] = {5, 6, 7, 8};
    #pragma unroll
    for (int d = 0; d < 4; d++) {
        int nsh = sh + fdr[d];
        int nsw = sw + fdc[d];
        bool inr = (nsh < SH && nsw >= 0 && nsw < SW);
        float r = 0.f;
        int ns = nsh * SW + nsw;
        if (inr) {
            const float4* nb = reinterpret_cast<const float4*>(
                g_tf + (size_t)(b * SP + ns) * CF);
            float4 b0 = nb[lane], b1 = nb[lane + 32];
            float dx;
            dx = a0.x - b0.x; r += dx*dx;
            dx = a0.y - b0.y; r += dx*dx;
            dx = a0.z - b0.z; r += dx*dx;
            dx = a0.w - b0.w; r += dx*dx;
            dx = a1.x - b1.x; r += dx*dx;
            dx = a1.y - b1.y; r += dx*dx;
            dx = a1.z - b1.z; r += dx*dx;
            dx = a1.w - b1.w; r += dx*dx;
        }
        #pragma unroll
        for (int o = 16; o > 0; o >>= 1) r += __shfl_xor_sync(0xffffffffu, r, o);
        if (lane == 0) {
            if (inr) {
                float e = expf(-r);
                simout[fk[d]] = e;
                g_sim[(size_t)(b * SP + ns) * 9 + (8 - fk[d])] = e;  // mirror
            } else {
                simout[fk[d]] = 0.f;
            }
        }
    }
}

// ---------------- K3: fused softmax + per-pixel main + final ----------------
__global__ void k_main(const float* __restrict__ logits,
                       const float* __restrict__ ori,
                       float* __restrict__ out) {
    __shared__ float sp[C * HALO_N];          // prob halo [c][r][col]
    __shared__ float rp[128], rn[128], rc[128];
    __shared__ int   sh_last;

    int tid = threadIdx.x;                    // 0..127
    int b   = blockIdx.z;
    int h0  = blockIdx.y * TH;
    int w0  = blockIdx.x * TW;
    int bid = (blockIdx.z * (H/TH) + blockIdx.y) * (W/TW) + blockIdx.x;

    // ---- load logits halo into shared ----
    const float* lb = logits + (size_t)b * C * HW;
    #pragma unroll
    for (int c = 0; c < C; c++) {
        for (int j = tid; j < HALO_N; j += 128) {
            int rr = j / HALO_W, cc = j % HALO_W;
            int gh = h0 - 1 + rr, gw = w0 - 1 + cc;
            float v = 0.f;
            if (gh >= 0 && gh < H && gw >= 0 && gw < W)
                v = lb[(size_t)c * HW + gh * W + gw];
            sp[c * HALO_N + j] = v;
        }
    }
    __syncthreads();

    // ---- softmax in shared (OOB pixels -> all-zero prob) ----
    for (int j = tid; j < HALO_N; j += 128) {
        int rr = j / HALO_W, cc = j % HALO_W;
        int gh = h0 - 1 + rr, gw = w0 - 1 + cc;
        bool inr = (gh >= 0 && gh < H && gw >= 0 && gw < W);
        float v[C];
        float m = -1e30f;
        #pragma unroll
        for (int c = 0; c < C; c++) { v[c] = sp[c * HALO_N + j]; m = fmaxf(m, v[c]); }
        float s = 0.f;
        #pragma unroll
        for (int c = 0; c < C; c++) { v[c] = expf(v[c] - m); s += v[c]; }
        float inv = inr ? (1.f / s) : 0.f;
        #pragma unroll
        for (int c = 0; c < C; c++) sp[c * HALO_N + j] = v[c] * inv;
    }
    __syncthreads();

    // ---- per-pixel main ----
    int lr = tid >> 4, lc = tid & 15;         // local coords in tile
    int h = h0 + lr, w = w0 + lc;
    int p = h * W + w;
    int sh2 = h >> 1, sw2 = w >> 1;
    int s   = sh2 * SW + sw2;

    int cbase = (lr + 1) * HALO_W + (lc + 1);
    float pc[C];
    float sump = 0.f;
    #pragma unroll
    for (int c = 0; c < C; c++) { pc[c] = sp[c * HALO_N + cbase]; sump += pc[c]; }

    const float* simrow = g_sim + (size_t)(b * SP + s) * 9;
    float sim[9], pos[9], neg[9];

    #pragma unroll
    for (int k = 0; k < 9; k++) {
        int dr = k / 3 - 1, dc = k % 3 - 1;
        int hn = h + dr, wn = w + dc;
        // prob dot from shared (OOB halo pixels hold zeros -> pos=0, neg=0)
        int nidx = cbase + dr * HALO_W + dc;
        float d = 0.f, sumq = 0.f;
        #pragma unroll
        for (int c = 0; c < C; c++) {
            float q = sp[c * HALO_N + nidx];
            d += pc[c] * q;
            sumq += q;
        }
        pos[k] = d;
        neg[k] = sump * sumq - d;
        if (hn < 0 || hn >= H || wn < 0 || wn >= W) {
            sim[k] = simrow[4];   // distance to zero-pad = ||f_center||^2
        } else {
            int dsh = (hn >> 1) - sh2, dsw = (wn >> 1) - sw2;
            sim[k] = (dsh == 0 && dsw == 0) ? 1.0f
                                            : simrow[(dsh + 1) * 3 + (dsw + 1)];
        }
    }

    float ssum = 0.f;
    #pragma unroll
    for (int k = 0; k < 9; k++) ssum += sim[k];
    out[2 + b * HW + p] = ssum * (1.f / 9.f);

    // top-5 by sim descending, stable ties (lower index first)
    bool used[9];
    #pragma unroll
    for (int k = 0; k < 9; k++) used[k] = false;
    float lp = 0.f;
    #pragma unroll
    for (int t = 0; t < 5; t++) {
        int bi = 0; float bv = -1e30f;
        #pragma unroll
        for (int k = 0; k < 9; k++)
            if (!used[k] && sim[k] > bv) { bv = sim[k]; bi = k; }
        used[bi] = true;
        lp += bv * (-pos[bi]);
    }
    // bottom-4 by sim ascending, stable ties (lower index first)
    bool used2[9];
    #pragma unroll
    for (int k = 0; k < 9; k++) used2[k] = false;
    float ln = 0.f;
    #pragma unroll
    for (int t = 0; t < 4; t++) {
        int bi = 0; float bv = 1e30f;
        #pragma unroll
        for (int k = 0; k < 9; k++)
            if (!used2[k] && sim[k] < bv) { bv = sim[k]; bi = k; }
        used2[bi] = true;
        ln += (1.f - bv) * (-neg[bi]);
    }

    float f0  = ori[(size_t)b * CF * SP + s];
    float msk = (f0 > 0.f) ? 1.f : 0.f;

    // ---- deterministic block reduction ----
    rp[tid] = msk * lp; rn[tid] = msk * ln; rc[tid] = msk;
    __syncthreads();
    #pragma unroll
    for (int o = 64; o > 0; o >>= 1) {
        if (tid < o) {
            rp[tid] += rp[tid + o];
            rn[tid] += rn[tid + o];
            rc[tid] += rc[tid + o];
        }
        __syncthreads();
    }
    if (tid == 0) {
        g_partial[bid]            = (double)rp[0];
        g_partial[NBLK + bid]     = (double)rn[0];
        g_partial[2 * NBLK + bid] = (double)rc[0];
        __threadfence();
        int v = atomicAdd(&g_count, 1);
        sh_last = (v == NBLK - 1) ? 1 : 0;
    }
    __syncthreads();

    // ---- last block: final deterministic reduction ----
    if (sh_last) {
        __shared__ double dp[128], dn[128], dc2[128];
        volatile double* gp = g_partial;
        dp[tid]  = gp[tid]            + gp[tid + 128];
        dn[tid]  = gp[NBLK + tid]     + gp[NBLK + tid + 128];
        dc2[tid] = gp[2 * NBLK + tid] + gp[2 * NBLK + tid + 128];
        __syncthreads();
        #pragma unroll
        for (int o = 64; o > 0; o >>= 1) {
            if (tid < o) { dp[tid] += dp[tid + o]; dn[tid] += dn[tid + o]; dc2[tid] += dc2[tid + o]; }
            __syncthreads();
        }
        if (tid == 0) {
            double cnt = dc2[0];
            out[0] = (float)(dp[0] / (cnt * 5.0));   // /(cnt*(TOP_K+1)) * W_POS
            out[1] = (float)(dn[0] / (cnt * 4.0));   // /(cnt*TOP_K)     * W_NEG
            g_count = 0;                              // reset for next replay
        }
    }
}

extern "C" void kernel_launch(void* const* d_in, const int* in_sizes, int n_in,
                              void* d_out, int out_size) {
    const float* ori;
    const float* logits;
    if (in_sizes[0] == BB * CF * SP) {
        ori    = (const float*)d_in[0];
        logits = (const float*)d_in[1];
    } else {
        ori    = (const float*)d_in[1];
        logits = (const float*)d_in[0];
    }
    float* out = (float*)d_out;

    dim3 tgrid(SP / 32, CF / 32, BB);
    k_transpose<<<tgrid, dim3(32, 32)>>>(ori);
    k_srcsim<<<(BB * SP * 32) / 256, 256>>>();
    dim3 mgrid(W / TW, H / TH, BB);
    k_main<<<mgrid, 128>>>(logits, ori, out);
}